// round 6
// baseline (speedup 1.0000x reference)
#include <cuda_runtime.h>
#include <cstddef>

#define NB 8
#define NC 512
#define NL 256                  // latent channels (L) — NOT 64!
#define NP 4096                 // spatial positions H*W
#define PLANE ((size_t)NL * NP) // one (mat,s,b) projection plane = 256*4096
#define BN_EPS 1e-5f
#define SIM_SCALE 0.0625f       // 256^-0.5

// g_kqv: [mat(3)*4+s][b(8)][flat plane 1048576]   (mat: 0=k,1=q,2=val)
__device__ float g_kqv[12ull * NB * NL * NP];
// g_ctx: [s(4)*NB+b][r(4096)][m(256)]
__device__ float g_ctx[(size_t)4 * NB * NP * NL];

// ---------------- Kernel P: projection GEMM + BN/bias epilogue --------------
// grid (16 p-tiles of 256, 12 = mat*4+s, 32 = b*4+ltile), 256 threads.
// Y[l, p] = sum_c W[l,c] * x[b,c,p], per-mat epilogue, write plane[l][p].
__global__ __launch_bounds__(256, 1)
void kp_proj(const float* __restrict__ x0, const float* __restrict__ x1,
             const float* __restrict__ x2, const float* __restrict__ x3,
             const float* __restrict__ Wk, const float* __restrict__ bk,
             const float* __restrict__ gk, const float* __restrict__ betak,
             const float* __restrict__ mk, const float* __restrict__ vk,
             const float* __restrict__ Wq, const float* __restrict__ bq,
             const float* __restrict__ gq, const float* __restrict__ betaq,
             const float* __restrict__ mq, const float* __restrict__ vq,
             const float* __restrict__ Wd, const float* __restrict__ bd)
{
    __shared__ float4 Xs4[32 * 64];        // [cc][p/4] : 32 channels x 256 p
    __shared__ float  Ws[64 * 33];         // [l_local][cc], padded stride 33

    const int p0  = blockIdx.x * 256;
    const int mat = blockIdx.y >> 2;
    const int s   = blockIdx.y & 3;
    const int b   = blockIdx.z >> 2;
    const int l0  = (blockIdx.z & 3) * 64;
    const int tid = threadIdx.x;
    const int tx  = tid & 31;              // p-group: p = tx*8 + j
    const int ty  = tid >> 5;              // l-group: l_local = ty*8 + i

    const float* xp = (s == 0) ? x0 : (s == 1) ? x1 : (s == 2) ? x2 : x3;
    const float* Wm = ((mat == 0) ? Wk : (mat == 1) ? Wq : Wd)
                      + (size_t)s * NL * NC + (size_t)l0 * NC;

    float acc[8][8];
    #pragma unroll
    for (int i = 0; i < 8; i++)
        #pragma unroll
        for (int j = 0; j < 8; j++) acc[i][j] = 0.f;

    #pragma unroll 1
    for (int c0 = 0; c0 < NC; c0 += 32) {
        // load X chunk: 32 channels x 256 p  (2048 float4 / 256 thr = 8 each)
        #pragma unroll
        for (int i = 0; i < 8; i++) {
            int flat4 = i * 256 + tid;
            int row   = flat4 >> 6;        // 0..31 channel-within-chunk
            int col4  = flat4 & 63;        // 0..63 (p/4)
            Xs4[row * 64 + col4] = *(const float4*)(
                xp + ((size_t)b * NC + c0 + row) * NP + p0 + col4 * 4);
        }
        // load W chunk: 64 l x 32 c  (512 float4 / 256 thr = 2 each)
        #pragma unroll
        for (int i = 0; i < 2; i++) {
            int flat4 = i * 256 + tid;
            int row   = flat4 >> 3;        // 0..63 l_local
            int col4  = flat4 & 7;         // 0..7  (c/4)
            const float4 v = *(const float4*)(Wm + (size_t)row * NC + c0 + col4 * 4);
            float* d = Ws + row * 33 + col4 * 4;
            d[0] = v.x; d[1] = v.y; d[2] = v.z; d[3] = v.w;
        }
        __syncthreads();

        #pragma unroll 8
        for (int kk = 0; kk < 32; kk++) {
            float a[8];
            #pragma unroll
            for (int i = 0; i < 8; i++) a[i] = Ws[(ty * 8 + i) * 33 + kk];
            float4 b0 = Xs4[kk * 64 + tx * 2];
            float4 b1 = Xs4[kk * 64 + tx * 2 + 1];
            float bv[8] = {b0.x, b0.y, b0.z, b0.w, b1.x, b1.y, b1.z, b1.w};
            #pragma unroll
            for (int i = 0; i < 8; i++)
                #pragma unroll
                for (int j = 0; j < 8; j++)
                    acc[i][j] = fmaf(a[i], bv[j], acc[i][j]);
        }
        __syncthreads();
    }

    // epilogue per mat; write plane [l][p]
    float* dst = g_kqv + (((size_t)(mat * 4 + s)) * NB + b) * PLANE;
    #pragma unroll
    for (int i = 0; i < 8; i++) {
        const int lg = l0 + ty * 8 + i;    // global l 0..255
        const int sl = s * NL + lg;
        float vout[8];
        if (mat == 0) {
            float sc = __ldg(gk + sl) * rsqrtf(__ldg(vk + sl) + BN_EPS);
            float sh = __ldg(betak + sl) + (__ldg(bk + sl) - __ldg(mk + sl)) * sc;
            #pragma unroll
            for (int j = 0; j < 8; j++) vout[j] = fmaxf(fmaf(acc[i][j], sc, sh), 0.f);
        } else if (mat == 1) {
            float sc = __ldg(gq + sl) * rsqrtf(__ldg(vq + sl) + BN_EPS);
            float sh = __ldg(betaq + sl) + (__ldg(bq + sl) - __ldg(mq + sl)) * sc;
            #pragma unroll
            for (int j = 0; j < 8; j++) vout[j] = fmaxf(fmaf(acc[i][j], sc, sh), 0.f);
        } else {
            float bb = __ldg(bd + sl);
            #pragma unroll
            for (int j = 0; j < 8; j++) vout[j] = acc[i][j] + bb;
        }
        float* drow = dst + (size_t)lg * NP + p0 + tx * 8;
        *(float4*)(drow)     = make_float4(vout[0], vout[1], vout[2], vout[3]);
        *(float4*)(drow + 4) = make_float4(vout[4], vout[5], vout[6], vout[7]);
    }
}

// ---------------- Kernel A: per-position 4x4 stream attention ---------------
// Raw-reshape identity: attention position r owns the 256 contiguous floats
// plane[r*256 .. r*256+256); output spatial index p = r. One warp per (b, r).
__global__ __launch_bounds__(256, 1)
void ka_attn()
{
    const int b    = blockIdx.y;
    const int warp = threadIdx.x >> 5;
    const int lane = threadIdx.x & 31;
    const int r    = blockIdx.x * 8 + warp;

    float qv[4][8], kv[4][8], vv[4][8];
    #pragma unroll
    for (int s = 0; s < 4; s++) {
        const float* kbp = g_kqv + (((size_t)(0 * 4 + s)) * NB + b) * PLANE + (size_t)r * NL;
        const float* qbp = g_kqv + (((size_t)(1 * 4 + s)) * NB + b) * PLANE + (size_t)r * NL;
        const float* vbp = g_kqv + (((size_t)(2 * 4 + s)) * NB + b) * PLANE + (size_t)r * NL;
        #pragma unroll
        for (int e = 0; e < 8; e++) {
            kv[s][e] = kbp[lane + e * 32];
            qv[s][e] = qbp[lane + e * 32];
            vv[s][e] = vbp[lane + e * 32];
        }
    }
    float sim[4][4];
    #pragma unroll
    for (int s = 0; s < 4; s++)
        #pragma unroll
        for (int t = 0; t < 4; t++) {
            float p = 0.f;
            #pragma unroll
            for (int e = 0; e < 8; e++) p = fmaf(qv[s][e], kv[t][e], p);
            #pragma unroll
            for (int off = 16; off > 0; off >>= 1)
                p += __shfl_xor_sync(0xffffffffu, p, off);
            sim[s][t] = p * SIM_SCALE;
        }
    float attn[4][4];
    #pragma unroll
    for (int s = 0; s < 4; s++) {
        float mx = fmaxf(fmaxf(sim[s][0], sim[s][1]), fmaxf(sim[s][2], sim[s][3]));
        float e0 = __expf(sim[s][0] - mx);
        float e1 = __expf(sim[s][1] - mx);
        float e2 = __expf(sim[s][2] - mx);
        float e3 = __expf(sim[s][3] - mx);
        float inv = 1.f / (e0 + e1 + e2 + e3);
        attn[s][0] = e0 * inv; attn[s][1] = e1 * inv;
        attn[s][2] = e2 * inv; attn[s][3] = e3 * inv;
    }
    #pragma unroll
    for (int s = 0; s < 4; s++) {
        float* dst = g_ctx + (((size_t)(s * NB + b)) * NP + r) * NL;
        #pragma unroll
        for (int e = 0; e < 8; e++) {
            float cv = attn[s][0] * vv[0][e] + attn[s][1] * vv[1][e]
                     + attn[s][2] * vv[2][e] + attn[s][3] * vv[3][e];
            dst[lane + e * 32] = cv;
        }
    }
}

// ---------------- Kernel U: up-projection + bias + residual -----------------
// out[s,b,c,p] = x_s[b,c,p] + bu[s,c] + sum_{m<256} ctx[sb,p,m] * Wu[s,c,m]
// grid (32 p-tiles, 4 c-tiles, 32 sb), 256 threads, tile 128c x 128p, K=256
// in chunks of 32.
#define KU_STRIDE 36

__global__ __launch_bounds__(256, 1)
void ku_up(const float* __restrict__ x0, const float* __restrict__ x1,
           const float* __restrict__ x2, const float* __restrict__ x3,
           const float* __restrict__ Wu, const float* __restrict__ bu,
           float* __restrict__ out)
{
    __shared__ float Wsm[128 * KU_STRIDE];  // [cl][mm] chunk
    __shared__ float Csm[128 * KU_STRIDE];  // [pl][mm] chunk

    const int sb = blockIdx.z;
    const int s  = sb >> 3;
    const int b  = sb & 7;
    const int c0 = blockIdx.y * 128;
    const int p0 = blockIdx.x * 128;
    const int tid = threadIdx.x;
    const int tx = tid & 15;                // pl = tx*8 + j
    const int ty = tid >> 4;                // cl = ty*8 + i

    float acc[8][8];
    #pragma unroll
    for (int i = 0; i < 8; i++)
        #pragma unroll
        for (int j = 0; j < 8; j++) acc[i][j] = 0.f;

    const float* ctxsrc = g_ctx + ((size_t)sb * NP + p0) * NL;

    #pragma unroll 1
    for (int m0 = 0; m0 < NL; m0 += 32) {
        // load Wu chunk: Wsm[cl][mm] = Wu[s, c0+cl, m0+mm]  (1024 f4 / 256 = 4)
        #pragma unroll
        for (int i = 0; i < 4; i++) {
            int flat4 = i * 256 + tid;
            int cl    = flat4 >> 3;         // 0..127
            int m4    = (flat4 & 7) * 4;    // 0..28
            const float4 v = *(const float4*)(
                Wu + ((size_t)s * NC + c0 + cl) * NL + m0 + m4);
            float* d = Wsm + cl * KU_STRIDE + m4;
            d[0]=v.x; d[1]=v.y; d[2]=v.z; d[3]=v.w;
        }
        // load ctx chunk: Csm[pl][mm] = ctx[sb, p0+pl, m0+mm]
        #pragma unroll
        for (int i = 0; i < 4; i++) {
            int flat4 = i * 256 + tid;
            int pl    = flat4 >> 3;
            int m4    = (flat4 & 7) * 4;
            const float4 v = *(const float4*)(ctxsrc + (size_t)pl * NL + m0 + m4);
            float* d = Csm + pl * KU_STRIDE + m4;
            d[0]=v.x; d[1]=v.y; d[2]=v.z; d[3]=v.w;
        }
        __syncthreads();

        #pragma unroll
        for (int m4 = 0; m4 < 32; m4 += 4) {
            float4 wv[8], cv[8];
            #pragma unroll
            for (int i = 0; i < 8; i++)
                wv[i] = *(const float4*)(Wsm + (ty * 8 + i) * KU_STRIDE + m4);
            #pragma unroll
            for (int j = 0; j < 8; j++)
                cv[j] = *(const float4*)(Csm + (tx * 8 + j) * KU_STRIDE + m4);
            #pragma unroll
            for (int i = 0; i < 8; i++)
                #pragma unroll
                for (int j = 0; j < 8; j++) {
                    float a = acc[i][j];
                    a = fmaf(wv[i].x, cv[j].x, a);
                    a = fmaf(wv[i].y, cv[j].y, a);
                    a = fmaf(wv[i].z, cv[j].z, a);
                    a = fmaf(wv[i].w, cv[j].w, a);
                    acc[i][j] = a;
                }
        }
        __syncthreads();
    }

    const float* xp = (s == 0) ? x0 : (s == 1) ? x1 : (s == 2) ? x2 : x3;
    #pragma unroll
    for (int i = 0; i < 8; i++) {
        const int cl = ty * 8 + i;
        const float bias = __ldg(bu + s * NC + c0 + cl);
        const float* xrow = xp + ((size_t)b * NC + c0 + cl) * NP + p0 + tx * 8;
        float* orow = out + ((size_t)sb * NC + c0 + cl) * NP + p0 + tx * 8;
        float4 xv0 = *(const float4*)(xrow);
        float4 xv1 = *(const float4*)(xrow + 4);
        float4 o0, o1;
        o0.x = xv0.x + bias + acc[i][0];
        o0.y = xv0.y + bias + acc[i][1];
        o0.z = xv0.z + bias + acc[i][2];
        o0.w = xv0.w + bias + acc[i][3];
        o1.x = xv1.x + bias + acc[i][4];
        o1.y = xv1.y + bias + acc[i][5];
        o1.z = xv1.z + bias + acc[i][6];
        o1.w = xv1.w + bias + acc[i][7];
        *(float4*)(orow)     = o0;
        *(float4*)(orow + 4) = o1;
    }
}

extern "C" void kernel_launch(void* const* d_in, const int* in_sizes, int n_in,
                              void* d_out, int out_size)
{
    const float* x0    = (const float*)d_in[0];
    const float* x1    = (const float*)d_in[1];
    const float* x2    = (const float*)d_in[2];
    const float* x3    = (const float*)d_in[3];
    const float* Wk    = (const float*)d_in[4];
    const float* bk    = (const float*)d_in[5];
    const float* gk    = (const float*)d_in[6];
    const float* betak = (const float*)d_in[7];
    const float* mk    = (const float*)d_in[8];
    const float* vk    = (const float*)d_in[9];
    const float* Wq    = (const float*)d_in[10];
    const float* bq    = (const float*)d_in[11];
    const float* gq    = (const float*)d_in[12];
    const float* betaq = (const float*)d_in[13];
    const float* mq    = (const float*)d_in[14];
    const float* vq    = (const float*)d_in[15];
    const float* Wd    = (const float*)d_in[16];
    const float* bd    = (const float*)d_in[17];
    const float* Wu    = (const float*)d_in[18];
    const float* bu    = (const float*)d_in[19];
    float* out = (float*)d_out;

    kp_proj<<<dim3(16, 12, 32), 256>>>(x0, x1, x2, x3,
                                       Wk, bk, gk, betak, mk, vk,
                                       Wq, bq, gq, betaq, mq, vq, Wd, bd);
    ka_attn<<<dim3(512, 8), 256>>>();
    ku_up<<<dim3(32, 4, 32), 256>>>(x0, x1, x2, x3, Wu, bu, out);
}

// round 7
// speedup vs baseline: 6.3256x; 6.3256x over previous
#include <cuda_runtime.h>
#include <cuda_bf16.h>
#include <cstdint>
#include <cstddef>

#define NB 8
#define NC 512
#define NL 256
#define NP 4096
#define PLANE ((size_t)NL * NP)     // 1048576
#define BN_EPS 1e-5f
#define SIM_SCALE 0.0625f           // 256^-0.5

// bf16 scratch
__device__ __nv_bfloat16 g_wbf[3ull * 4 * NL * NC];        // [mat][s][l][c]
__device__ __nv_bfloat16 g_wubf[4ull * NC * NL];           // [s][c][m]
__device__ __nv_bfloat16 g_xbf[4ull * NB * NC * NP];       // [s][b][c][p]
__device__ __nv_bfloat16 g_kqvb[12ull * NB * PLANE];       // [mat*4+s][b][l][p]
__device__ __nv_bfloat16 g_ctxb[(size_t)4 * NB * NP * NL]; // [sb][r][m]

// ---------------- helpers ---------------------------------------------------
__device__ __forceinline__ uint32_t smem_u32(const void* p) {
    return (uint32_t)__cvta_generic_to_shared(p);
}
__device__ __forceinline__ void ldsm_x4(uint32_t& r0, uint32_t& r1,
                                        uint32_t& r2, uint32_t& r3, uint32_t a) {
    asm volatile("ldmatrix.sync.aligned.m8n8.x4.shared.b16 {%0,%1,%2,%3}, [%4];"
                 : "=r"(r0), "=r"(r1), "=r"(r2), "=r"(r3) : "r"(a));
}
__device__ __forceinline__ void ldsm_x4t(uint32_t& r0, uint32_t& r1,
                                         uint32_t& r2, uint32_t& r3, uint32_t a) {
    asm volatile("ldmatrix.sync.aligned.m8n8.x4.trans.shared.b16 {%0,%1,%2,%3}, [%4];"
                 : "=r"(r0), "=r"(r1), "=r"(r2), "=r"(r3) : "r"(a));
}
__device__ __forceinline__ void mma_bf16(float* c, const uint32_t* a,
                                         uint32_t b0, uint32_t b1) {
    asm volatile(
        "mma.sync.aligned.m16n8k16.row.col.f32.bf16.bf16.f32 "
        "{%0,%1,%2,%3},{%4,%5,%6,%7},{%8,%9},{%0,%1,%2,%3};"
        : "+f"(c[0]), "+f"(c[1]), "+f"(c[2]), "+f"(c[3])
        : "r"(a[0]), "r"(a[1]), "r"(a[2]), "r"(a[3]), "r"(b0), "r"(b1));
}

// ---------------- conversion kernels ----------------------------------------
__global__ void kconv_w(const float* __restrict__ Wk, const float* __restrict__ Wq,
                        const float* __restrict__ Wd, const float* __restrict__ Wu)
{
    const size_t i = (size_t)blockIdx.x * blockDim.x + threadIdx.x;
    const size_t nw = 4ull * NL * NC;       // 524288
    if (i < nw) {
        g_wbf[0 * nw + i] = __float2bfloat16(Wk[i]);
        g_wbf[1 * nw + i] = __float2bfloat16(Wq[i]);
        g_wbf[2 * nw + i] = __float2bfloat16(Wd[i]);
        g_wubf[i]         = __float2bfloat16(Wu[i]);   // also 4*512*256 = 524288
    }
}

__global__ void kconv_x(const float* __restrict__ x0, const float* __restrict__ x1,
                        const float* __restrict__ x2, const float* __restrict__ x3)
{
    const int s = blockIdx.y;
    const float* xp = (s == 0) ? x0 : (s == 1) ? x1 : (s == 2) ? x2 : x3;
    __nv_bfloat16* dst = g_xbf + (size_t)s * NB * NC * NP;
    const size_t n4 = (size_t)NB * NC * NP / 4;   // 4194304 float4
    for (size_t i = (size_t)blockIdx.x * blockDim.x + threadIdx.x;
         i < n4; i += (size_t)gridDim.x * blockDim.x) {
        float4 v = *(const float4*)(xp + i * 4);
        __nv_bfloat162 lo = __floats2bfloat162_rn(v.x, v.y);
        __nv_bfloat162 hi = __floats2bfloat162_rn(v.z, v.w);
        uint2 pk;
        pk.x = *(uint32_t*)&lo;
        pk.y = *(uint32_t*)&hi;
        *(uint2*)(dst + i * 4) = pk;
    }
}

// ---------------- Kernel P: projection GEMM (tensor core) -------------------
// C[l 128 x p 128] = W[l x 512] * X[512 x p] for one (mat,s,b,ltile).
// grid (32 ptiles, 12 = mat*4+s, 16 = b*2+ltile), 256 threads (8 warps 2x4).
#define SA 40    // Wsm row stride (bf16), 32 + 8 pad
#define SB 136   // Xsm row stride (bf16), 128 + 8 pad

__global__ __launch_bounds__(256)
void kp_proj(const float* __restrict__ bk,
             const float* __restrict__ gk, const float* __restrict__ betak,
             const float* __restrict__ mk, const float* __restrict__ vk,
             const float* __restrict__ bq,
             const float* __restrict__ gq, const float* __restrict__ betaq,
             const float* __restrict__ mq, const float* __restrict__ vq,
             const float* __restrict__ bd)
{
    __shared__ __nv_bfloat16 Wsm[128 * SA];
    __shared__ __nv_bfloat16 Xsm[32 * SB];

    const int p0  = blockIdx.x * 128;
    const int mat = blockIdx.y >> 2;
    const int s   = blockIdx.y & 3;
    const int b   = blockIdx.z >> 1;
    const int l0  = (blockIdx.z & 1) * 128;
    const int tid = threadIdx.x;
    const int warp = tid >> 5, lane = tid & 31;
    const int wm = warp >> 2, wn = warp & 3;

    const __nv_bfloat16* wsrc = g_wbf + ((size_t)mat * 4 + s) * (NL * NC)
                                      + (size_t)l0 * NC;
    const __nv_bfloat16* xsrc = g_xbf + ((size_t)(s * NB + b)) * (NC * NP);

    float acc[4][4][4];
    #pragma unroll
    for (int i = 0; i < 4; i++)
        #pragma unroll
        for (int j = 0; j < 4; j++)
            #pragma unroll
            for (int r = 0; r < 4; r++) acc[i][j][r] = 0.f;

    const uint32_t wbase = smem_u32(Wsm);
    const uint32_t xbase = smem_u32(Xsm);

    #pragma unroll 1
    for (int c0 = 0; c0 < NC; c0 += 32) {
        // W tile: 128 l x 32 c  (512 x 16B / 256 thr = 2 each)
        #pragma unroll
        for (int it = 0; it < 2; it++) {
            int f = it * 256 + tid;
            int row = f >> 2, c8 = (f & 3) * 8;
            *(uint4*)(Wsm + row * SA + c8) =
                *(const uint4*)(wsrc + (size_t)row * NC + c0 + c8);
        }
        // X tile: 32 c x 128 p
        #pragma unroll
        for (int it = 0; it < 2; it++) {
            int f = it * 256 + tid;
            int row = f >> 4, pc = (f & 15) * 8;
            *(uint4*)(Xsm + row * SB + pc) =
                *(const uint4*)(xsrc + (size_t)(c0 + row) * NP + p0 + pc);
        }
        __syncthreads();

        #pragma unroll
        for (int k0 = 0; k0 < 32; k0 += 16) {
            uint32_t a[4][4];
            #pragma unroll
            for (int mt = 0; mt < 4; mt++) {
                uint32_t addr = wbase +
                    ((wm * 64 + mt * 16 + (lane & 15)) * SA + k0 + ((lane & 16) >> 1)) * 2;
                ldsm_x4(a[mt][0], a[mt][1], a[mt][2], a[mt][3], addr);
            }
            uint32_t bb[4][2];
            #pragma unroll
            for (int ntp = 0; ntp < 2; ntp++) {
                uint32_t addr = xbase +
                    ((k0 + (lane & 15)) * SB + wn * 32 + ntp * 16 + ((lane & 16) >> 1)) * 2;
                uint32_t r0, r1, r2, r3;
                ldsm_x4t(r0, r1, r2, r3, addr);
                bb[ntp * 2 + 0][0] = r0; bb[ntp * 2 + 0][1] = r1;
                bb[ntp * 2 + 1][0] = r2; bb[ntp * 2 + 1][1] = r3;
            }
            #pragma unroll
            for (int mt = 0; mt < 4; mt++)
                #pragma unroll
                for (int nt = 0; nt < 4; nt++)
                    mma_bf16(acc[mt][nt], a[mt], bb[nt][0], bb[nt][1]);
        }
        __syncthreads();
    }

    // epilogue: BN/bias per l, write bf16 plane [l][p]
    __nv_bfloat16* plane = g_kqvb + (((size_t)(mat * 4 + s)) * NB + b) * PLANE;
    #pragma unroll
    for (int mt = 0; mt < 4; mt++)
        #pragma unroll
        for (int half = 0; half < 2; half++) {
            const int l  = l0 + wm * 64 + mt * 16 + (lane >> 2) + half * 8;
            const int sl = s * NL + l;
            float sc, sh;
            if (mat == 0) {
                sc = __ldg(gk + sl) * rsqrtf(__ldg(vk + sl) + BN_EPS);
                sh = __ldg(betak + sl) + (__ldg(bk + sl) - __ldg(mk + sl)) * sc;
            } else if (mat == 1) {
                sc = __ldg(gq + sl) * rsqrtf(__ldg(vq + sl) + BN_EPS);
                sh = __ldg(betaq + sl) + (__ldg(bq + sl) - __ldg(mq + sl)) * sc;
            } else {
                sc = 1.f;
                sh = __ldg(bd + sl);
            }
            #pragma unroll
            for (int nt = 0; nt < 4; nt++) {
                const int p = p0 + wn * 32 + nt * 8 + (lane & 3) * 2;
                float v0 = acc[mt][nt][half * 2 + 0];
                float v1 = acc[mt][nt][half * 2 + 1];
                v0 = fmaf(v0, sc, sh);
                v1 = fmaf(v1, sc, sh);
                if (mat < 2) { v0 = fmaxf(v0, 0.f); v1 = fmaxf(v1, 0.f); }
                __nv_bfloat162 pk = __floats2bfloat162_rn(v0, v1);
                *(uint32_t*)(plane + (size_t)l * NP + p) = *(uint32_t*)&pk;
            }
        }
}

// ---------------- Kernel A: per-position 4x4 stream attention ---------------
// One warp per (b, r); bf16 in/out, fp32 math.
__global__ __launch_bounds__(256)
void ka_attn()
{
    const int b    = blockIdx.y;
    const int warp = threadIdx.x >> 5;
    const int lane = threadIdx.x & 31;
    const int r    = blockIdx.x * 8 + warp;

    float2 qv[4][4], kv[4][4], vv[4][4];
    #pragma unroll
    for (int s = 0; s < 4; s++) {
        const __nv_bfloat162* kb = (const __nv_bfloat162*)
            (g_kqvb + (((size_t)(0 * 4 + s)) * NB + b) * PLANE + (size_t)r * NL);
        const __nv_bfloat162* qb = (const __nv_bfloat162*)
            (g_kqvb + (((size_t)(1 * 4 + s)) * NB + b) * PLANE + (size_t)r * NL);
        const __nv_bfloat162* vb = (const __nv_bfloat162*)
            (g_kqvb + (((size_t)(2 * 4 + s)) * NB + b) * PLANE + (size_t)r * NL);
        #pragma unroll
        for (int e = 0; e < 4; e++) {
            kv[s][e] = __bfloat1622float2(kb[lane + e * 32]);
            qv[s][e] = __bfloat1622float2(qb[lane + e * 32]);
            vv[s][e] = __bfloat1622float2(vb[lane + e * 32]);
        }
    }
    float sim[4][4];
    #pragma unroll
    for (int s = 0; s < 4; s++)
        #pragma unroll
        for (int t = 0; t < 4; t++) {
            float p = 0.f;
            #pragma unroll
            for (int e = 0; e < 4; e++) {
                p = fmaf(qv[s][e].x, kv[t][e].x, p);
                p = fmaf(qv[s][e].y, kv[t][e].y, p);
            }
            #pragma unroll
            for (int off = 16; off > 0; off >>= 1)
                p += __shfl_xor_sync(0xffffffffu, p, off);
            sim[s][t] = p * SIM_SCALE;
        }
    float attn[4][4];
    #pragma unroll
    for (int s = 0; s < 4; s++) {
        float mx = fmaxf(fmaxf(sim[s][0], sim[s][1]), fmaxf(sim[s][2], sim[s][3]));
        float e0 = __expf(sim[s][0] - mx);
        float e1 = __expf(sim[s][1] - mx);
        float e2 = __expf(sim[s][2] - mx);
        float e3 = __expf(sim[s][3] - mx);
        float inv = 1.f / (e0 + e1 + e2 + e3);
        attn[s][0] = e0 * inv; attn[s][1] = e1 * inv;
        attn[s][2] = e2 * inv; attn[s][3] = e3 * inv;
    }
    #pragma unroll
    for (int s = 0; s < 4; s++) {
        __nv_bfloat162* dst = (__nv_bfloat162*)
            (g_ctxb + (((size_t)(s * NB + b)) * NP + r) * NL);
        #pragma unroll
        for (int e = 0; e < 4; e++) {
            float cx = attn[s][0] * vv[0][e].x + attn[s][1] * vv[1][e].x
                     + attn[s][2] * vv[2][e].x + attn[s][3] * vv[3][e].x;
            float cy = attn[s][0] * vv[0][e].y + attn[s][1] * vv[1][e].y
                     + attn[s][2] * vv[2][e].y + attn[s][3] * vv[3][e].y;
            dst[lane + e * 32] = __floats2bfloat162_rn(cx, cy);
        }
    }
}

// ---------------- Kernel U: up-projection + bias + residual (tensor core) ---
// C[c 128 x p 128] = Wu[c x 256] * ctx^T[256 x p]; ctx stored [p][m] -> B via
// non-trans ldmatrix. grid (32 ptiles, 4 ctiles, 32 sb), 256 thr (8 warps 2x4).
#define SC 40

__global__ __launch_bounds__(256)
void ku_up(const float* __restrict__ x0, const float* __restrict__ x1,
           const float* __restrict__ x2, const float* __restrict__ x3,
           const float* __restrict__ bu, float* __restrict__ out)
{
    __shared__ __nv_bfloat16 Wsm[128 * SC];
    __shared__ __nv_bfloat16 Csm[128 * SC];

    const int sb = blockIdx.z;
    const int s  = sb >> 3;
    const int b  = sb & 7;
    const int c0b = blockIdx.y * 128;
    const int p0  = blockIdx.x * 128;
    const int tid = threadIdx.x;
    const int warp = tid >> 5, lane = tid & 31;
    const int wm = warp >> 2, wn = warp & 3;

    const __nv_bfloat16* wsrc = g_wubf + ((size_t)s * NC + c0b) * NL;
    const __nv_bfloat16* csrc = g_ctxb + ((size_t)sb * NP + p0) * NL;

    float acc[4][4][4];
    #pragma unroll
    for (int i = 0; i < 4; i++)
        #pragma unroll
        for (int j = 0; j < 4; j++)
            #pragma unroll
            for (int r = 0; r < 4; r++) acc[i][j][r] = 0.f;

    const uint32_t wbase = smem_u32(Wsm);
    const uint32_t cbase = smem_u32(Csm);

    #pragma unroll 1
    for (int m0 = 0; m0 < NL; m0 += 32) {
        #pragma unroll
        for (int it = 0; it < 2; it++) {
            int f = it * 256 + tid;
            int row = f >> 2, m8 = (f & 3) * 8;
            *(uint4*)(Wsm + row * SC + m8) =
                *(const uint4*)(wsrc + (size_t)row * NL + m0 + m8);
            *(uint4*)(Csm + row * SC + m8) =
                *(const uint4*)(csrc + (size_t)row * NL + m0 + m8);
        }
        __syncthreads();

        #pragma unroll
        for (int k0 = 0; k0 < 32; k0 += 16) {
            uint32_t a[4][4];
            #pragma unroll
            for (int mt = 0; mt < 4; mt++) {
                uint32_t addr = wbase +
                    ((wm * 64 + mt * 16 + (lane & 15)) * SC + k0 + ((lane & 16) >> 1)) * 2;
                ldsm_x4(a[mt][0], a[mt][1], a[mt][2], a[mt][3], addr);
            }
            uint32_t bb[4][2];
            #pragma unroll
            for (int ntp = 0; ntp < 2; ntp++) {
                uint32_t addr = cbase +
                    ((wn * 32 + ntp * 16 + (lane & 7) + ((lane & 16) >> 1)) * SC
                     + k0 + (lane & 8)) * 2;
                uint32_t r0, r1, r2, r3;
                ldsm_x4(r0, r1, r2, r3, addr);
                bb[ntp * 2 + 0][0] = r0; bb[ntp * 2 + 0][1] = r1;
                bb[ntp * 2 + 1][0] = r2; bb[ntp * 2 + 1][1] = r3;
            }
            #pragma unroll
            for (int mt = 0; mt < 4; mt++)
                #pragma unroll
                for (int nt = 0; nt < 4; nt++)
                    mma_bf16(acc[mt][nt], a[mt], bb[nt][0], bb[nt][1]);
        }
        __syncthreads();
    }

    const float* xp = (s == 0) ? x0 : (s == 1) ? x1 : (s == 2) ? x2 : x3;
    #pragma unroll
    for (int mt = 0; mt < 4; mt++)
        #pragma unroll
        for (int half = 0; half < 2; half++) {
            const int c = c0b + wm * 64 + mt * 16 + (lane >> 2) + half * 8;
            const float bias = __ldg(bu + s * NC + c);
            const float* xrow = xp + ((size_t)b * NC + c) * NP + p0;
            float* orow = out + ((size_t)sb * NC + c) * NP + p0;
            #pragma unroll
            for (int nt = 0; nt < 4; nt++) {
                const int p = wn * 32 + nt * 8 + (lane & 3) * 2;
                float2 xv = *(const float2*)(xrow + p);
                float2 o;
                o.x = xv.x + bias + acc[mt][nt][half * 2 + 0];
                o.y = xv.y + bias + acc[mt][nt][half * 2 + 1];
                *(float2*)(orow + p) = o;
            }
        }
}

extern "C" void kernel_launch(void* const* d_in, const int* in_sizes, int n_in,
                              void* d_out, int out_size)
{
    const float* x0    = (const float*)d_in[0];
    const float* x1    = (const float*)d_in[1];
    const float* x2    = (const float*)d_in[2];
    const float* x3    = (const float*)d_in[3];
    const float* Wk    = (const float*)d_in[4];
    const float* bk    = (const float*)d_in[5];
    const float* gk    = (const float*)d_in[6];
    const float* betak = (const float*)d_in[7];
    const float* mk    = (const float*)d_in[8];
    const float* vk    = (const float*)d_in[9];
    const float* Wq    = (const float*)d_in[10];
    const float* bq    = (const float*)d_in[11];
    const float* gq    = (const float*)d_in[12];
    const float* betaq = (const float*)d_in[13];
    const float* mq    = (const float*)d_in[14];
    const float* vq    = (const float*)d_in[15];
    const float* Wd    = (const float*)d_in[16];
    const float* bd    = (const float*)d_in[17];
    const float* Wu    = (const float*)d_in[18];
    const float* bu    = (const float*)d_in[19];
    float* out = (float*)d_out;

    kconv_w<<<2048, 256>>>(Wk, Wq, Wd, Wu);
    kconv_x<<<dim3(4096, 4), 256>>>(x0, x1, x2, x3);
    kp_proj<<<dim3(32, 12, 16), 256>>>(bk, gk, betak, mk, vk,
                                       bq, gq, betaq, mq, vq, bd);
    ka_attn<<<dim3(512, 8), 256>>>();
    ku_up<<<dim3(32, 4, 32), 256>>>(x0, x1, x2, x3, bu, out);
}